// round 1
// baseline (speedup 1.0000x reference)
#include <cuda_runtime.h>
#include <math.h>

#define B   2
#define T   2048
#define D   1024
#define NH  16
#define NKV 4
#define HD  64
#define GQ  4            // NH / NKV
#define EPSF 1.1920929e-07f

// ---------------- scratch (no allocations allowed) ----------------
__device__ float g_q[B*T*NH*HD];     // q projection -> normed/roped/gained q
__device__ float g_k[B*T*NKV*HD];    // k projection -> normed/roped k
__device__ float g_v[B*T*NKV*HD];    // v projection -> mixed v
__device__ float g_y[B*T*NH*HD];     // attention output (gate folded in)
__device__ float g_gate[B*T*NH];     // sigmoid gate per (b,t,head)

__device__ __forceinline__ float* scratch_buf(int id) {
    switch (id) {
        case 0: return g_q;
        case 1: return g_k;
        case 2: return g_v;
        default: return g_y;
    }
}

// ---------------- generic SGEMM: C[M,N] = A[M,K] @ W[N,K]^T ----------------
// 64x64 block tile, K-slice 16, 256 threads, 4x4 microtile per thread.
__global__ __launch_bounds__(256)
void sgemm_nt(const float* __restrict__ Aext, int Abuf,
              const float* __restrict__ W,
              float* __restrict__ Cext, int Cbuf,
              int M, int N, int K) {
    const float* A = Aext ? Aext : scratch_buf(Abuf);
    float*       C = Cext ? Cext : scratch_buf(Cbuf);

    __shared__ float As[64][17];
    __shared__ float Ws[64][17];

    const int tid = threadIdx.x;
    const int tx = tid & 15, ty = tid >> 4;
    const int m0 = blockIdx.y * 64, n0 = blockIdx.x * 64;

    const int lr = tid >> 2;          // load row 0..63
    const int lk = (tid & 3) * 4;     // load k offset 0,4,8,12

    float acc[4][4] = {};

    for (int k0 = 0; k0 < K; k0 += 16) {
        float4 a = *(const float4*)(A + (size_t)(m0 + lr) * K + k0 + lk);
        float4 w = *(const float4*)(W + (size_t)(n0 + lr) * K + k0 + lk);
        As[lr][lk+0] = a.x; As[lr][lk+1] = a.y; As[lr][lk+2] = a.z; As[lr][lk+3] = a.w;
        Ws[lr][lk+0] = w.x; Ws[lr][lk+1] = w.y; Ws[lr][lk+2] = w.z; Ws[lr][lk+3] = w.w;
        __syncthreads();
        #pragma unroll
        for (int kk = 0; kk < 16; kk++) {
            float av[4], wv[4];
            #pragma unroll
            for (int i = 0; i < 4; i++) av[i] = As[ty*4+i][kk];
            #pragma unroll
            for (int j = 0; j < 4; j++) wv[j] = Ws[tx*4+j][kk];
            #pragma unroll
            for (int i = 0; i < 4; i++)
                #pragma unroll
                for (int j = 0; j < 4; j++)
                    acc[i][j] += av[i] * wv[j];
        }
        __syncthreads();
    }
    #pragma unroll
    for (int i = 0; i < 4; i++)
        #pragma unroll
        for (int j = 0; j < 4; j++)
            C[(size_t)(m0 + ty*4 + i) * N + (n0 + tx*4 + j)] = acc[i][j];
}

// ---------------- V epilogue: raw_v = vproj + ve ; v = l0*v0 + l1*raw ----------------
__global__ void v_epilogue(const float* __restrict__ ve, const float* __restrict__ v0,
                           const float* __restrict__ lam, float* __restrict__ raw_out) {
    int i = blockIdx.x * 256 + threadIdx.x;
    float raw = g_v[i] + ve[i];
    raw_out[i] = raw;
    g_v[i] = lam[0] * v0[i] + lam[1] * raw;
}

// ---------------- RMSNorm + RoPE (+ per-head gain) in place; one warp per row ----------------
__global__ void rmsnorm_rope(int buf, const float* __restrict__ gain, int H, double nb) {
    float* base = scratch_buf(buf);
    int row  = blockIdx.x * 8 + (threadIdx.x >> 5);
    int lane = threadIdx.x & 31;
    int t = (row / H) % T;
    int h = row % H;
    float* p = base + (size_t)row * HD;

    float a  = p[lane];
    float b2 = p[lane + 32];
    float ss = a*a + b2*b2;
    #pragma unroll
    for (int o = 16; o; o >>= 1) ss += __shfl_xor_sync(0xffffffffu, ss, o);
    float r = rsqrtf(ss * (1.0f/HD) + EPSF);
    a *= r; b2 *= r;

    // inv freq, fp32-rounded like JAX, then accurate trig of the fp32 angle
    float inv = (float)pow(nb, -(double)(2*lane) / (double)HD);
    float fr  = (float)t * inv;
    float c = (float)cos((double)fr);
    float s = (float)sin((double)fr);

    float o1 =  a*c + b2*s;
    float o2 = -a*s + b2*c;
    if (gain) { float gg = gain[h]; o1 *= gg; o2 *= gg; }
    p[lane]      = o1;
    p[lane + 32] = o2;
}

// ---------------- gate: sigmoid(x @ gate_w^T + gate_b), one block per (b,t) ----------------
__global__ void gate_kernel(const float* __restrict__ x, const float* __restrict__ gw,
                            const float* __restrict__ gb) {
    __shared__ float xs[D];
    int bt = blockIdx.x;
    for (int i = threadIdx.x; i < D; i += 512) xs[i] = x[(size_t)bt * D + i];
    __syncthreads();
    int h = threadIdx.x >> 5, lane = threadIdx.x & 31;
    const float* w = gw + (size_t)h * D;
    float s = 0.f;
    for (int i = lane; i < D; i += 32) s += xs[i] * w[i];
    #pragma unroll
    for (int o = 16; o; o >>= 1) s += __shfl_xor_sync(0xffffffffu, s, o);
    if (lane == 0) g_gate[bt * NH + h] = 1.0f / (1.0f + __expf(-(s + gb[h])));
}

// ---------------- causal flash attention, 64-q tile x 32-kv tile, gate folded ----------------
#define KT 32
__global__ __launch_bounds__(256)
void attn_kernel() {
    __shared__ float Qs[64][HD];
    __shared__ float Ks[KT][HD + 1];   // pad -> conflict-free K reads
    __shared__ float Vs[KT][HD];
    __shared__ float ps[8][KT];

    const int qt = blockIdx.x, h = blockIdx.y, b = blockIdx.z;
    const int kv = h / GQ;
    const int tid = threadIdx.x;
    const int w = tid >> 5, lane = tid & 31;

    for (int i = tid; i < 64 * HD; i += 256) {
        int r = i >> 6, d = i & 63;
        Qs[r][d] = g_q[((size_t)(b*T + qt*64 + r) * NH + h) * HD + d];
    }

    float o0[8], o1[8], m[8], l[8];
    #pragma unroll
    for (int i = 0; i < 8; i++) { o0[i] = 0.f; o1[i] = 0.f; m[i] = -3.4e38f; l[i] = 0.f; }

    const int nt = 2*qt + 2;
    for (int kt = 0; kt < nt; kt++) {
        const int t0 = kt * KT;
        __syncthreads();
        for (int i = tid; i < KT * HD; i += 256) {
            int r = i >> 6, d = i & 63;
            size_t base = ((size_t)(b*T + t0 + r) * NKV + kv) * HD + d;
            Ks[r][d] = g_k[base];
            Vs[r][d] = g_v[base];
        }
        __syncthreads();

        for (int rr = 0; rr < 8; rr++) {
            int r = w*8 + rr;
            int qrow = qt*64 + r;
            int col = t0 + lane;
            bool valid = (col <= qrow);
            float s = -3.4e38f;
            if (valid) {
                float acc = 0.f;
                #pragma unroll
                for (int d = 0; d < HD; d++) acc += Qs[r][d] * Ks[lane][d];
                s = acc * 0.125f;   // 1/sqrt(64)
            }
            float mx = s;
            #pragma unroll
            for (int o = 16; o; o >>= 1) mx = fmaxf(mx, __shfl_xor_sync(0xffffffffu, mx, o));
            float mnew  = fmaxf(m[rr], mx);
            float pv    = valid ? __expf(s - mnew) : 0.f;
            float alpha = __expf(m[rr] - mnew);
            m[rr] = mnew;
            float ls = pv;
            #pragma unroll
            for (int o = 16; o; o >>= 1) ls += __shfl_xor_sync(0xffffffffu, ls, o);
            l[rr] = l[rr] * alpha + ls;

            ps[w][lane] = pv;
            __syncwarp();
            float a0 = o0[rr] * alpha, a1 = o1[rr] * alpha;
            #pragma unroll
            for (int c = 0; c < KT; c++) {
                float pc = ps[w][c];
                a0 += pc * Vs[c][lane];
                a1 += pc * Vs[c][lane + 32];
            }
            o0[rr] = a0; o1[rr] = a1;
            __syncwarp();
        }
    }

    #pragma unroll
    for (int rr = 0; rr < 8; rr++) {
        int r = w*8 + rr;
        int grow = b*T + qt*64 + r;
        float inv = g_gate[grow * NH + h] / l[rr];
        size_t base = ((size_t)grow * NH + h) * HD;
        g_y[base + lane]      = o0[rr] * inv;
        g_y[base + lane + 32] = o1[rr] * inv;
    }
}

// ---------------- launch ----------------
extern "C" void kernel_launch(void* const* d_in, const int* in_sizes, int n_in,
                              void* d_out, int out_size) {
    (void)in_sizes; (void)n_in; (void)out_size;
    const float* x  = (const float*)d_in[0];
    const float* qw = (const float*)d_in[1];
    const float* kw = (const float*)d_in[2];
    const float* vw = (const float*)d_in[3];
    const float* ow = (const float*)d_in[4];
    const float* ve = (const float*)d_in[5];
    const float* v0 = (const float*)d_in[6];
    const float* qg = (const float*)d_in[7];
    const float* vl = (const float*)d_in[8];
    const float* gw = (const float*)d_in[9];
    const float* gb = (const float*)d_in[10];

    float* out     = (float*)d_out;
    float* raw_out = out + (size_t)B * T * D;     // second output: raw_v

    // NTK-scaled base: T=2048 > TSL=1024
    const double nb = 10000.0 * pow((double)T / 1024.0, 64.0 / 62.0);

    // projections
    sgemm_nt<<<dim3((NH*HD)/64,  (B*T)/64), 256>>>(x, -1, qw, nullptr, 0, B*T, NH*HD,  D);
    sgemm_nt<<<dim3((NKV*HD)/64, (B*T)/64), 256>>>(x, -1, kw, nullptr, 1, B*T, NKV*HD, D);
    sgemm_nt<<<dim3((NKV*HD)/64, (B*T)/64), 256>>>(x, -1, vw, nullptr, 2, B*T, NKV*HD, D);

    // v residual mix + raw_v output
    v_epilogue<<<(B*T*NKV*HD)/256, 256>>>(ve, v0, vl, raw_out);

    // rmsnorm + rope (+ q gain)
    rmsnorm_rope<<<(B*T*NH)/8,  256>>>(0, qg,      NH,  nb);
    rmsnorm_rope<<<(B*T*NKV)/8, 256>>>(1, nullptr, NKV, nb);

    // gate
    gate_kernel<<<B*T, 512>>>(x, gw, gb);

    // attention (gate folded into epilogue)
    attn_kernel<<<dim3(T/64, NH, B), 256>>>();

    // output projection
    sgemm_nt<<<dim3(D/64, (B*T)/64), 256>>>(nullptr, 3, ow, out, -1, B*T, D, D);
}

// round 2
// speedup vs baseline: 1.1682x; 1.1682x over previous
#include <cuda_runtime.h>
#include <math.h>
#include <stdint.h>

#define B   2
#define T   2048
#define D   1024
#define NH  16
#define NKV 4
#define HD  64
#define GQ  4            // NH / NKV
#define EPSF 1.1920929e-07f

// ---------------- scratch (no allocations allowed) ----------------
__device__ float g_q[B*T*NH*HD];     // q projection -> normed/roped/gained q
__device__ float g_k[B*T*NKV*HD];    // k projection -> normed/roped k
__device__ float g_v[B*T*NKV*HD];    // v projection -> mixed v
__device__ float g_y[B*T*NH*HD];     // attention output (gate folded in)
__device__ float g_gate[B*T*NH];     // sigmoid gate per (b,t,head)

__device__ __forceinline__ float* scratch_buf(int id) {
    switch (id) {
        case 0: return g_q;
        case 1: return g_k;
        case 2: return g_v;
        default: return g_y;
    }
}

// ---------------- tf32 helpers ----------------
__device__ __forceinline__ float to_tf32(float x) {
    float r;
    asm("cvt.rna.tf32.f32 %0, %1;" : "=f"(r) : "f"(x));
    return r;
}

__device__ __forceinline__ void mma_tf32(float* c, const uint32_t* a, const uint32_t* b) {
    asm volatile(
        "mma.sync.aligned.m16n8k8.row.col.f32.tf32.tf32.f32 "
        "{%0,%1,%2,%3}, {%4,%5,%6,%7}, {%8,%9}, {%0,%1,%2,%3};\n"
        : "+f"(c[0]), "+f"(c[1]), "+f"(c[2]), "+f"(c[3])
        : "r"(a[0]), "r"(a[1]), "r"(a[2]), "r"(a[3]), "r"(b[0]), "r"(b[1]));
}

// ---------------- tf32 tensor-core GEMM: C[M,N] = A[M,K] @ W[N,K]^T ----------------
// CTA tile 128x128, BK=16, 256 threads (8 warps, 2x4), warp tile 64x32.
// Smem rows padded to stride 20 floats -> all fragment LDS conflict-free.
#define GSTRIDE 20
__global__ __launch_bounds__(256)
void tf32_gemm(const float* __restrict__ Aext, int Abuf,
               const float* __restrict__ W,
               float* __restrict__ Cext, int Cbuf,
               int M, int N, int K) {
    const float* A = Aext ? Aext : scratch_buf(Abuf);
    float*       C = Cext ? Cext : scratch_buf(Cbuf);

    __shared__ float As[2][128 * GSTRIDE];
    __shared__ float Bs[2][128 * GSTRIDE];

    const int tid  = threadIdx.x;
    const int lane = tid & 31;
    const int w    = tid >> 5;
    const int wm   = w & 1;      // 0..1  (64 rows each)
    const int wn   = w >> 1;     // 0..3  (32 cols each)
    const int tq   = lane >> 2;  // 0..7
    const int tr   = lane & 3;   // 0..3

    const int m0 = blockIdx.y * 128;
    const int n0 = blockIdx.x * 128;

    const int lrow = tid >> 2;         // 0..63
    const int lcol = (tid & 3) * 4;    // 0,4,8,12

    const float* aN = A + (size_t)(m0 + lrow) * K + lcol;
    const float* bN = W + (size_t)(n0 + lrow) * K + lcol;

    float c[16][4];
    #pragma unroll
    for (int i = 0; i < 16; i++)
        #pragma unroll
        for (int j = 0; j < 4; j++) c[i][j] = 0.f;

    // preload tile 0
    {
        float4 a0 = *(const float4*)(aN);
        float4 a1 = *(const float4*)(aN + (size_t)64 * K);
        float4 b0 = *(const float4*)(bN);
        float4 b1 = *(const float4*)(bN + (size_t)64 * K);
        float* as = As[0]; float* bs = Bs[0];
        int o0 = lrow * GSTRIDE + lcol;
        int o1 = (lrow + 64) * GSTRIDE + lcol;
        as[o0+0]=to_tf32(a0.x); as[o0+1]=to_tf32(a0.y); as[o0+2]=to_tf32(a0.z); as[o0+3]=to_tf32(a0.w);
        as[o1+0]=to_tf32(a1.x); as[o1+1]=to_tf32(a1.y); as[o1+2]=to_tf32(a1.z); as[o1+3]=to_tf32(a1.w);
        bs[o0+0]=to_tf32(b0.x); bs[o0+1]=to_tf32(b0.y); bs[o0+2]=to_tf32(b0.z); bs[o0+3]=to_tf32(b0.w);
        bs[o1+0]=to_tf32(b1.x); bs[o1+1]=to_tf32(b1.y); bs[o1+2]=to_tf32(b1.z); bs[o1+3]=to_tf32(b1.w);
    }
    __syncthreads();

    const int niter = K / 16;
    int cur = 0;
    for (int it = 0; it < niter; it++) {
        // prefetch next k-slice to registers
        float4 pa0, pa1, pb0, pb1;
        const bool has_next = (it + 1 < niter);
        if (has_next) {
            int k0 = (it + 1) * 16;
            pa0 = *(const float4*)(aN + k0);
            pa1 = *(const float4*)(aN + (size_t)64 * K + k0);
            pb0 = *(const float4*)(bN + k0);
            pb1 = *(const float4*)(bN + (size_t)64 * K + k0);
        }

        // compute on current buffer
        const float* as = As[cur];
        const float* bs = Bs[cur];
        #pragma unroll
        for (int ks = 0; ks < 2; ks++) {
            const int kb = ks * 8;
            uint32_t af[4][4], bf[4][2];
            #pragma unroll
            for (int mi = 0; mi < 4; mi++) {
                int r = wm * 64 + mi * 16 + tq;
                af[mi][0] = __float_as_uint(as[r * GSTRIDE + kb + tr]);
                af[mi][1] = __float_as_uint(as[(r + 8) * GSTRIDE + kb + tr]);
                af[mi][2] = __float_as_uint(as[r * GSTRIDE + kb + tr + 4]);
                af[mi][3] = __float_as_uint(as[(r + 8) * GSTRIDE + kb + tr + 4]);
            }
            #pragma unroll
            for (int ni = 0; ni < 4; ni++) {
                int nrow = wn * 32 + ni * 8 + tq;
                bf[ni][0] = __float_as_uint(bs[nrow * GSTRIDE + kb + tr]);
                bf[ni][1] = __float_as_uint(bs[nrow * GSTRIDE + kb + tr + 4]);
            }
            #pragma unroll
            for (int mi = 0; mi < 4; mi++)
                #pragma unroll
                for (int ni = 0; ni < 4; ni++)
                    mma_tf32(c[mi * 4 + ni], af[mi], bf[ni]);
        }

        if (has_next) {
            int nxt = cur ^ 1;
            float* asx = As[nxt]; float* bsx = Bs[nxt];
            int o0 = lrow * GSTRIDE + lcol;
            int o1 = (lrow + 64) * GSTRIDE + lcol;
            asx[o0+0]=to_tf32(pa0.x); asx[o0+1]=to_tf32(pa0.y); asx[o0+2]=to_tf32(pa0.z); asx[o0+3]=to_tf32(pa0.w);
            asx[o1+0]=to_tf32(pa1.x); asx[o1+1]=to_tf32(pa1.y); asx[o1+2]=to_tf32(pa1.z); asx[o1+3]=to_tf32(pa1.w);
            bsx[o0+0]=to_tf32(pb0.x); bsx[o0+1]=to_tf32(pb0.y); bsx[o0+2]=to_tf32(pb0.z); bsx[o0+3]=to_tf32(pb0.w);
            bsx[o1+0]=to_tf32(pb1.x); bsx[o1+1]=to_tf32(pb1.y); bsx[o1+2]=to_tf32(pb1.z); bsx[o1+3]=to_tf32(pb1.w);
            __syncthreads();
            cur = nxt;
        }
    }

    // epilogue
    #pragma unroll
    for (int mi = 0; mi < 4; mi++) {
        #pragma unroll
        for (int ni = 0; ni < 4; ni++) {
            int row = m0 + wm * 64 + mi * 16 + tq;
            int col = n0 + wn * 32 + ni * 8 + 2 * tr;
            float* cp = c[mi * 4 + ni];
            *(float2*)(C + (size_t)row * N + col)       = make_float2(cp[0], cp[1]);
            *(float2*)(C + (size_t)(row + 8) * N + col) = make_float2(cp[2], cp[3]);
        }
    }
}

// ---------------- V epilogue: raw_v = vproj + ve ; v = l0*v0 + l1*raw ----------------
__global__ void v_epilogue(const float* __restrict__ ve, const float* __restrict__ v0,
                           const float* __restrict__ lam, float* __restrict__ raw_out) {
    int i = blockIdx.x * 256 + threadIdx.x;
    float raw = g_v[i] + ve[i];
    raw_out[i] = raw;
    g_v[i] = lam[0] * v0[i] + lam[1] * raw;
}

// ---------------- RMSNorm + RoPE (+ per-head gain) in place; one warp per row ----------------
__global__ void rmsnorm_rope(int buf, const float* __restrict__ gain, int H, double nb) {
    float* base = scratch_buf(buf);
    int row  = blockIdx.x * 8 + (threadIdx.x >> 5);
    int lane = threadIdx.x & 31;
    int t = (row / H) % T;
    int h = row % H;
    float* p = base + (size_t)row * HD;

    float a  = p[lane];
    float b2 = p[lane + 32];
    float ss = a*a + b2*b2;
    #pragma unroll
    for (int o = 16; o; o >>= 1) ss += __shfl_xor_sync(0xffffffffu, ss, o);
    float r = rsqrtf(ss * (1.0f/HD) + EPSF);
    a *= r; b2 *= r;

    float inv = (float)pow(nb, -(double)(2*lane) / (double)HD);
    float fr  = (float)t * inv;
    float c = (float)cos((double)fr);
    float s = (float)sin((double)fr);

    float o1 =  a*c + b2*s;
    float o2 = -a*s + b2*c;
    if (gain) { float gg = gain[h]; o1 *= gg; o2 *= gg; }
    p[lane]      = o1;
    p[lane + 32] = o2;
}

// ---------------- gate: sigmoid(x @ gate_w^T + gate_b), one block per (b,t) ----------------
__global__ void gate_kernel(const float* __restrict__ x, const float* __restrict__ gw,
                            const float* __restrict__ gb) {
    __shared__ float xs[D];
    int bt = blockIdx.x;
    for (int i = threadIdx.x; i < D; i += 512) xs[i] = x[(size_t)bt * D + i];
    __syncthreads();
    int h = threadIdx.x >> 5, lane = threadIdx.x & 31;
    const float* w = gw + (size_t)h * D;
    float s = 0.f;
    for (int i = lane; i < D; i += 32) s += xs[i] * w[i];
    #pragma unroll
    for (int o = 16; o; o >>= 1) s += __shfl_xor_sync(0xffffffffu, s, o);
    if (lane == 0) g_gate[bt * NH + h] = 1.0f / (1.0f + __expf(-(s + gb[h])));
}

// ---------------- causal flash attention, 64-q tile x 32-kv tile, gate folded ----------------
#define KT 32
__global__ __launch_bounds__(256)
void attn_kernel() {
    __shared__ float Qs[64][HD];
    __shared__ float Ks[KT][HD + 1];   // pad -> conflict-free K reads
    __shared__ float Vs[KT][HD];
    __shared__ float ps[8][KT];

    const int qt = blockIdx.x, h = blockIdx.y, b = blockIdx.z;
    const int kv = h / GQ;
    const int tid = threadIdx.x;
    const int w = tid >> 5, lane = tid & 31;

    for (int i = tid; i < 64 * HD; i += 256) {
        int r = i >> 6, d = i & 63;
        Qs[r][d] = g_q[((size_t)(b*T + qt*64 + r) * NH + h) * HD + d];
    }

    float o0[8], o1[8], m[8], l[8];
    #pragma unroll
    for (int i = 0; i < 8; i++) { o0[i] = 0.f; o1[i] = 0.f; m[i] = -3.4e38f; l[i] = 0.f; }

    const int nt = 2*qt + 2;
    for (int kt = 0; kt < nt; kt++) {
        const int t0 = kt * KT;
        __syncthreads();
        for (int i = tid; i < KT * HD; i += 256) {
            int r = i >> 6, d = i & 63;
            size_t base = ((size_t)(b*T + t0 + r) * NKV + kv) * HD + d;
            Ks[r][d] = g_k[base];
            Vs[r][d] = g_v[base];
        }
        __syncthreads();

        for (int rr = 0; rr < 8; rr++) {
            int r = w*8 + rr;
            int qrow = qt*64 + r;
            int col = t0 + lane;
            bool valid = (col <= qrow);
            float s = -3.4e38f;
            if (valid) {
                float acc = 0.f;
                #pragma unroll
                for (int d = 0; d < HD; d++) acc += Qs[r][d] * Ks[lane][d];
                s = acc * 0.125f;   // 1/sqrt(64)
            }
            float mx = s;
            #pragma unroll
            for (int o = 16; o; o >>= 1) mx = fmaxf(mx, __shfl_xor_sync(0xffffffffu, mx, o));
            float mnew  = fmaxf(m[rr], mx);
            float pv    = valid ? __expf(s - mnew) : 0.f;
            float alpha = __expf(m[rr] - mnew);
            m[rr] = mnew;
            float ls = pv;
            #pragma unroll
            for (int o = 16; o; o >>= 1) ls += __shfl_xor_sync(0xffffffffu, ls, o);
            l[rr] = l[rr] * alpha + ls;

            ps[w][lane] = pv;
            __syncwarp();
            float a0 = o0[rr] * alpha, a1 = o1[rr] * alpha;
            #pragma unroll
            for (int c = 0; c < KT; c++) {
                float pc = ps[w][c];
                a0 += pc * Vs[c][lane];
                a1 += pc * Vs[c][lane + 32];
            }
            o0[rr] = a0; o1[rr] = a1;
            __syncwarp();
        }
    }

    #pragma unroll
    for (int rr = 0; rr < 8; rr++) {
        int r = w*8 + rr;
        int grow = b*T + qt*64 + r;
        float inv = g_gate[grow * NH + h] / l[rr];
        size_t base = ((size_t)grow * NH + h) * HD;
        g_y[base + lane]      = o0[rr] * inv;
        g_y[base + lane + 32] = o1[rr] * inv;
    }
}

// ---------------- launch ----------------
extern "C" void kernel_launch(void* const* d_in, const int* in_sizes, int n_in,
                              void* d_out, int out_size) {
    (void)in_sizes; (void)n_in; (void)out_size;
    const float* x  = (const float*)d_in[0];
    const float* qw = (const float*)d_in[1];
    const float* kw = (const float*)d_in[2];
    const float* vw = (const float*)d_in[3];
    const float* ow = (const float*)d_in[4];
    const float* ve = (const float*)d_in[5];
    const float* v0 = (const float*)d_in[6];
    const float* qg = (const float*)d_in[7];
    const float* vl = (const float*)d_in[8];
    const float* gw = (const float*)d_in[9];
    const float* gb = (const float*)d_in[10];

    float* out     = (float*)d_out;
    float* raw_out = out + (size_t)B * T * D;     // second output: raw_v

    // NTK-scaled base: T=2048 > TSL=1024
    const double nb = 10000.0 * pow((double)T / 1024.0, 64.0 / 62.0);

    // projections (tf32 tensor cores)
    tf32_gemm<<<dim3((NH*HD)/128,  (B*T)/128), 256>>>(x, -1, qw, nullptr, 0, B*T, NH*HD,  D);
    tf32_gemm<<<dim3((NKV*HD)/128, (B*T)/128), 256>>>(x, -1, kw, nullptr, 1, B*T, NKV*HD, D);
    tf32_gemm<<<dim3((NKV*HD)/128, (B*T)/128), 256>>>(x, -1, vw, nullptr, 2, B*T, NKV*HD, D);

    // v residual mix + raw_v output
    v_epilogue<<<(B*T*NKV*HD)/256, 256>>>(ve, v0, vl, raw_out);

    // rmsnorm + rope (+ q gain)
    rmsnorm_rope<<<(B*T*NH)/8,  256>>>(0, qg,      NH,  nb);
    rmsnorm_rope<<<(B*T*NKV)/8, 256>>>(1, nullptr, NKV, nb);

    // gate
    gate_kernel<<<B*T, 512>>>(x, gw, gb);

    // attention (gate folded into epilogue)
    attn_kernel<<<dim3(T/64, NH, B), 256>>>();

    // output projection (tf32 tensor cores)
    tf32_gemm<<<dim3(D/128, (B*T)/128), 256>>>(nullptr, 3, ow, out, -1, B*T, D, D);
}

// round 3
// speedup vs baseline: 2.0222x; 1.7311x over previous
#include <cuda_runtime.h>
#include <math.h>
#include <stdint.h>

#define B   2
#define T   2048
#define D   1024
#define NH  16
#define NKV 4
#define HD  64
#define GQ  4            // NH / NKV
#define EPSF 1.1920929e-07f
#define LOG2E 1.4426950408889634f

// ---------------- scratch (no allocations allowed) ----------------
__device__ float g_q[B*T*NH*HD];     // q projection -> normed/roped/gained q
__device__ float g_k[B*T*NKV*HD];    // k projection -> normed/roped k
__device__ float g_v[B*T*NKV*HD];    // v projection -> mixed v
__device__ float g_y[B*T*NH*HD];     // attention output (gate folded in)
__device__ float g_gate[B*T*NH];     // sigmoid gate per (b,t,head)

__device__ __forceinline__ float* scratch_buf(int id) {
    switch (id) {
        case 0: return g_q;
        case 1: return g_k;
        case 2: return g_v;
        default: return g_y;
    }
}

// ---------------- tf32 helpers ----------------
__device__ __forceinline__ float to_tf32(float x) {
    float r;
    asm("cvt.rna.tf32.f32 %0, %1;" : "=f"(r) : "f"(x));
    return r;
}

__device__ __forceinline__ void mma_tf32(float* c, const uint32_t* a, const uint32_t* b) {
    asm volatile(
        "mma.sync.aligned.m16n8k8.row.col.f32.tf32.tf32.f32 "
        "{%0,%1,%2,%3}, {%4,%5,%6,%7}, {%8,%9}, {%0,%1,%2,%3};\n"
        : "+f"(c[0]), "+f"(c[1]), "+f"(c[2]), "+f"(c[3])
        : "r"(a[0]), "r"(a[1]), "r"(a[2]), "r"(a[3]), "r"(b[0]), "r"(b[1]));
}

// split x into tf32 hi + tf32 lo
__device__ __forceinline__ void split_tf32(float x, uint32_t& hi, uint32_t& lo) {
    float h = to_tf32(x);
    hi = __float_as_uint(h);
    lo = __float_as_uint(to_tf32(x - h));
}

// ---------------- tf32 3-pass GEMM: C[M,N] = A[M,K] @ W[N,K]^T (fp32-accurate) ----------------
// CTA tile 128x128, BK=16, 256 threads (8 warps, 2x4), warp tile 64x32.
#define GSTRIDE 20
__global__ __launch_bounds__(256)
void tf32_gemm3(const float* __restrict__ Aext, int Abuf,
                const float* __restrict__ W,
                float* __restrict__ Cext, int Cbuf,
                int M, int N, int K) {
    const float* A = Aext ? Aext : scratch_buf(Abuf);
    float*       C = Cext ? Cext : scratch_buf(Cbuf);

    __shared__ float As[2][128 * GSTRIDE];
    __shared__ float Bs[2][128 * GSTRIDE];

    const int tid  = threadIdx.x;
    const int lane = tid & 31;
    const int w    = tid >> 5;
    const int wm   = w & 1;
    const int wn   = w >> 1;
    const int tq   = lane >> 2;
    const int tr   = lane & 3;

    const int m0 = blockIdx.y * 128;
    const int n0 = blockIdx.x * 128;

    const int lrow = tid >> 2;
    const int lcol = (tid & 3) * 4;

    const float* aN = A + (size_t)(m0 + lrow) * K + lcol;
    const float* bN = W + (size_t)(n0 + lrow) * K + lcol;

    float c[16][4];
    #pragma unroll
    for (int i = 0; i < 16; i++)
        #pragma unroll
        for (int j = 0; j < 4; j++) c[i][j] = 0.f;

    {
        float4 a0 = *(const float4*)(aN);
        float4 a1 = *(const float4*)(aN + (size_t)64 * K);
        float4 b0 = *(const float4*)(bN);
        float4 b1 = *(const float4*)(bN + (size_t)64 * K);
        float* as = As[0]; float* bs = Bs[0];
        int o0 = lrow * GSTRIDE + lcol;
        int o1 = (lrow + 64) * GSTRIDE + lcol;
        as[o0+0]=a0.x; as[o0+1]=a0.y; as[o0+2]=a0.z; as[o0+3]=a0.w;
        as[o1+0]=a1.x; as[o1+1]=a1.y; as[o1+2]=a1.z; as[o1+3]=a1.w;
        bs[o0+0]=b0.x; bs[o0+1]=b0.y; bs[o0+2]=b0.z; bs[o0+3]=b0.w;
        bs[o1+0]=b1.x; bs[o1+1]=b1.y; bs[o1+2]=b1.z; bs[o1+3]=b1.w;
    }
    __syncthreads();

    const int niter = K / 16;
    int cur = 0;
    for (int it = 0; it < niter; it++) {
        float4 pa0, pa1, pb0, pb1;
        const bool has_next = (it + 1 < niter);
        if (has_next) {
            int k0 = (it + 1) * 16;
            pa0 = *(const float4*)(aN + k0);
            pa1 = *(const float4*)(aN + (size_t)64 * K + k0);
            pb0 = *(const float4*)(bN + k0);
            pb1 = *(const float4*)(bN + (size_t)64 * K + k0);
        }

        const float* as = As[cur];
        const float* bs = Bs[cur];
        #pragma unroll
        for (int ks = 0; ks < 2; ks++) {
            const int kb = ks * 8;
            uint32_t ah[4][4], al[4][4], bh[4][2], bl[4][2];
            #pragma unroll
            for (int mi = 0; mi < 4; mi++) {
                int r = wm * 64 + mi * 16 + tq;
                split_tf32(as[r * GSTRIDE + kb + tr],           ah[mi][0], al[mi][0]);
                split_tf32(as[(r + 8) * GSTRIDE + kb + tr],     ah[mi][1], al[mi][1]);
                split_tf32(as[r * GSTRIDE + kb + tr + 4],       ah[mi][2], al[mi][2]);
                split_tf32(as[(r + 8) * GSTRIDE + kb + tr + 4], ah[mi][3], al[mi][3]);
            }
            #pragma unroll
            for (int ni = 0; ni < 4; ni++) {
                int nrow = wn * 32 + ni * 8 + tq;
                split_tf32(bs[nrow * GSTRIDE + kb + tr],     bh[ni][0], bl[ni][0]);
                split_tf32(bs[nrow * GSTRIDE + kb + tr + 4], bh[ni][1], bl[ni][1]);
            }
            #pragma unroll
            for (int mi = 0; mi < 4; mi++)
                #pragma unroll
                for (int ni = 0; ni < 4; ni++) {
                    mma_tf32(c[mi * 4 + ni], ah[mi], bh[ni]);
                    mma_tf32(c[mi * 4 + ni], ah[mi], bl[ni]);
                    mma_tf32(c[mi * 4 + ni], al[mi], bh[ni]);
                }
        }

        if (has_next) {
            int nxt = cur ^ 1;
            float* asx = As[nxt]; float* bsx = Bs[nxt];
            int o0 = lrow * GSTRIDE + lcol;
            int o1 = (lrow + 64) * GSTRIDE + lcol;
            asx[o0+0]=pa0.x; asx[o0+1]=pa0.y; asx[o0+2]=pa0.z; asx[o0+3]=pa0.w;
            asx[o1+0]=pa1.x; asx[o1+1]=pa1.y; asx[o1+2]=pa1.z; asx[o1+3]=pa1.w;
            bsx[o0+0]=pb0.x; bsx[o0+1]=pb0.y; bsx[o0+2]=pb0.z; bsx[o0+3]=pb0.w;
            bsx[o1+0]=pb1.x; bsx[o1+1]=pb1.y; bsx[o1+2]=pb1.z; bsx[o1+3]=pb1.w;
            __syncthreads();
            cur = nxt;
        }
    }

    #pragma unroll
    for (int mi = 0; mi < 4; mi++) {
        #pragma unroll
        for (int ni = 0; ni < 4; ni++) {
            int row = m0 + wm * 64 + mi * 16 + tq;
            int col = n0 + wn * 32 + ni * 8 + 2 * tr;
            float* cp = c[mi * 4 + ni];
            *(float2*)(C + (size_t)row * N + col)       = make_float2(cp[0], cp[1]);
            *(float2*)(C + (size_t)(row + 8) * N + col) = make_float2(cp[2], cp[3]);
        }
    }
}

// ---------------- V epilogue: raw_v = vproj + ve ; v = l0*v0 + l1*raw ----------------
__global__ void v_epilogue(const float* __restrict__ ve, const float* __restrict__ v0,
                           const float* __restrict__ lam, float* __restrict__ raw_out) {
    int i = blockIdx.x * 256 + threadIdx.x;
    float raw = g_v[i] + ve[i];
    raw_out[i] = raw;
    g_v[i] = lam[0] * v0[i] + lam[1] * raw;
}

// ---------------- RMSNorm + RoPE (+ per-head gain) in place; one warp per row ----------------
__global__ void rmsnorm_rope(int buf, const float* __restrict__ gain, int H, double nb) {
    float* base = scratch_buf(buf);
    int row  = blockIdx.x * 8 + (threadIdx.x >> 5);
    int lane = threadIdx.x & 31;
    int t = (row / H) % T;
    int h = row % H;
    float* p = base + (size_t)row * HD;

    float a  = p[lane];
    float b2 = p[lane + 32];
    float ss = a*a + b2*b2;
    #pragma unroll
    for (int o = 16; o; o >>= 1) ss += __shfl_xor_sync(0xffffffffu, ss, o);
    float r = rsqrtf(ss * (1.0f/HD) + EPSF);
    a *= r; b2 *= r;

    float inv = (float)pow(nb, -(double)(2*lane) / (double)HD);
    float fr  = (float)t * inv;
    float c = (float)cos((double)fr);
    float s = (float)sin((double)fr);

    float o1 =  a*c + b2*s;
    float o2 = -a*s + b2*c;
    if (gain) { float gg = gain[h]; o1 *= gg; o2 *= gg; }
    p[lane]      = o1;
    p[lane + 32] = o2;
}

// ---------------- gate: sigmoid(x @ gate_w^T + gate_b), one block per (b,t) ----------------
__global__ void gate_kernel(const float* __restrict__ x, const float* __restrict__ gw,
                            const float* __restrict__ gb) {
    __shared__ float xs[D];
    int bt = blockIdx.x;
    for (int i = threadIdx.x; i < D; i += 512) xs[i] = x[(size_t)bt * D + i];
    __syncthreads();
    int h = threadIdx.x >> 5, lane = threadIdx.x & 31;
    const float* w = gw + (size_t)h * D;
    float s = 0.f;
    for (int i = lane; i < D; i += 32) s += xs[i] * w[i];
    #pragma unroll
    for (int o = 16; o; o >>= 1) s += __shfl_xor_sync(0xffffffffu, s, o);
    if (lane == 0) g_gate[bt * NH + h] = 1.0f / (1.0f + __expf(-(s + gb[h])));
}

// ---------------- tensor-core causal flash attention ----------------
// 4 warps, 64 q rows per CTA (16/warp), 64-kv tiles. tf32 3-pass MMAs,
// fp32 online softmax in fragments, gate folded into epilogue.
__global__ __launch_bounds__(128)
void attn_mma() {
    __shared__ float Ks[64][68];   // pad 68: fragment LDS conflict-free
    __shared__ float Vs[64][72];   // pad 72: fragment LDS conflict-free

    const int qt = blockIdx.x, h = blockIdx.y, b = blockIdx.z;
    const int kv = h / GQ;
    const int tid = threadIdx.x;
    const int w = tid >> 5, lane = tid & 31;
    const int tq = lane >> 2, tr = lane & 3;
    const int r0 = w * 16 + tq;      // warp-local q row (and +8)

    // ---- stage Q tile into Ks, build persistent hi/lo Q fragments ----
    for (int i = tid; i < 64 * 16; i += 128) {
        int r = i >> 4, c4 = (i & 15) * 4;
        float4 v = *(const float4*)(g_q + ((size_t)(b*T + qt*64 + r) * NH + h) * HD + c4);
        Ks[r][c4] = v.x; Ks[r][c4+1] = v.y; Ks[r][c4+2] = v.z; Ks[r][c4+3] = v.w;
    }
    __syncthreads();

    uint32_t qhi[8][4], qlo[8][4];
    #pragma unroll
    for (int kb = 0; kb < 8; kb++) {
        split_tf32(Ks[r0][kb*8 + tr],       qhi[kb][0], qlo[kb][0]);
        split_tf32(Ks[r0 + 8][kb*8 + tr],   qhi[kb][1], qlo[kb][1]);
        split_tf32(Ks[r0][kb*8 + tr + 4],   qhi[kb][2], qlo[kb][2]);
        split_tf32(Ks[r0 + 8][kb*8 + tr+4], qhi[kb][3], qlo[kb][3]);
    }
    __syncthreads();

    float o[8][4];
    #pragma unroll
    for (int ni = 0; ni < 8; ni++)
        #pragma unroll
        for (int j = 0; j < 4; j++) o[ni][j] = 0.f;
    float m0r = -1e30f, m1r = -1e30f, l0r = 0.f, l1r = 0.f;

    const int ntiles = qt + 1;
    for (int kt = 0; kt < ntiles; kt++) {
        const int t0 = kt * 64;
        __syncthreads();
        for (int i = tid; i < 64 * 16; i += 128) {
            int r = i >> 4, c4 = (i & 15) * 4;
            size_t base = ((size_t)(b*T + t0 + r) * NKV + kv) * HD + c4;
            float4 kk = *(const float4*)(g_k + base);
            float4 vv = *(const float4*)(g_v + base);
            Ks[r][c4] = kk.x; Ks[r][c4+1] = kk.y; Ks[r][c4+2] = kk.z; Ks[r][c4+3] = kk.w;
            Vs[r][c4] = vv.x; Vs[r][c4+1] = vv.y; Vs[r][c4+2] = vv.z; Vs[r][c4+3] = vv.w;
        }
        __syncthreads();

        // ---- scores S = Q @ K^T (3-pass tf32) ----
        float s[8][4];
        #pragma unroll
        for (int ni = 0; ni < 8; ni++) {
            s[ni][0] = s[ni][1] = s[ni][2] = s[ni][3] = 0.f;
            #pragma unroll
            for (int kb = 0; kb < 8; kb++) {
                uint32_t bh[2], bl[2];
                split_tf32(Ks[ni*8 + tq][kb*8 + tr],     bh[0], bl[0]);
                split_tf32(Ks[ni*8 + tq][kb*8 + tr + 4], bh[1], bl[1]);
                mma_tf32(s[ni], qhi[kb], bh);
                mma_tf32(s[ni], qhi[kb], bl);
                mma_tf32(s[ni], qlo[kb], bh);
            }
        }

        // ---- causal mask (diagonal tile only) ----
        const int rowa = qt*64 + r0, rowb = rowa + 8;
        if (kt == qt) {
            #pragma unroll
            for (int ni = 0; ni < 8; ni++) {
                int col = t0 + ni*8 + 2*tr;
                if (col     > rowa) s[ni][0] = -1e30f;
                if (col + 1 > rowa) s[ni][1] = -1e30f;
                if (col     > rowb) s[ni][2] = -1e30f;
                if (col + 1 > rowb) s[ni][3] = -1e30f;
            }
        }

        // ---- online softmax (logits = s * 0.125) ----
        const float SC = 0.125f;
        float mx0 = -1e30f, mx1 = -1e30f;
        #pragma unroll
        for (int ni = 0; ni < 8; ni++) {
            mx0 = fmaxf(mx0, fmaxf(s[ni][0], s[ni][1]));
            mx1 = fmaxf(mx1, fmaxf(s[ni][2], s[ni][3]));
        }
        mx0 = fmaxf(mx0, __shfl_xor_sync(0xffffffffu, mx0, 1));
        mx0 = fmaxf(mx0, __shfl_xor_sync(0xffffffffu, mx0, 2));
        mx1 = fmaxf(mx1, __shfl_xor_sync(0xffffffffu, mx1, 1));
        mx1 = fmaxf(mx1, __shfl_xor_sync(0xffffffffu, mx1, 2));
        float mn0 = fmaxf(m0r, mx0 * SC);
        float mn1 = fmaxf(m1r, mx1 * SC);
        float al0 = exp2f((m0r - mn0) * LOG2E);
        float al1 = exp2f((m1r - mn1) * LOG2E);
        m0r = mn0; m1r = mn1;

        float sum0 = 0.f, sum1 = 0.f;
        #pragma unroll
        for (int ni = 0; ni < 8; ni++) {
            float p0 = exp2f((s[ni][0] * SC - mn0) * LOG2E);
            float p1 = exp2f((s[ni][1] * SC - mn0) * LOG2E);
            float p2 = exp2f((s[ni][2] * SC - mn1) * LOG2E);
            float p3 = exp2f((s[ni][3] * SC - mn1) * LOG2E);
            s[ni][0] = p0; s[ni][1] = p1; s[ni][2] = p2; s[ni][3] = p3;
            sum0 += p0 + p1; sum1 += p2 + p3;
            o[ni][0] *= al0; o[ni][1] *= al0; o[ni][2] *= al1; o[ni][3] *= al1;
        }
        sum0 += __shfl_xor_sync(0xffffffffu, sum0, 1);
        sum0 += __shfl_xor_sync(0xffffffffu, sum0, 2);
        sum1 += __shfl_xor_sync(0xffffffffu, sum1, 1);
        sum1 += __shfl_xor_sync(0xffffffffu, sum1, 2);
        l0r = l0r * al0 + sum0;
        l1r = l1r * al1 + sum1;

        // ---- O += P @ V (3-pass tf32); C->A fragment conversion via shuffles ----
        const int basel = lane & ~3;
        #pragma unroll
        for (int c0 = 0; c0 < 8; c0++) {
            const int srcA = basel + (tr >> 1);
            const int srcB = srcA + 2;
            float pa0 = __shfl_sync(0xffffffffu, s[c0][0], srcA);
            float pa1 = __shfl_sync(0xffffffffu, s[c0][1], srcA);
            float pa2 = __shfl_sync(0xffffffffu, s[c0][2], srcA);
            float pa3 = __shfl_sync(0xffffffffu, s[c0][3], srcA);
            float pb0 = __shfl_sync(0xffffffffu, s[c0][0], srcB);
            float pb1 = __shfl_sync(0xffffffffu, s[c0][1], srcB);
            float pb2 = __shfl_sync(0xffffffffu, s[c0][2], srcB);
            float pb3 = __shfl_sync(0xffffffffu, s[c0][3], srcB);
            bool odd = (tr & 1);
            float a0 = odd ? pa1 : pa0;   // P[tq][8c0+tr]
            float a1 = odd ? pa3 : pa2;   // P[tq+8][8c0+tr]
            float a2 = odd ? pb1 : pb0;   // P[tq][8c0+tr+4]
            float a3 = odd ? pb3 : pb2;   // P[tq+8][8c0+tr+4]
            uint32_t ph[4], pl[4];
            split_tf32(a0, ph[0], pl[0]);
            split_tf32(a1, ph[1], pl[1]);
            split_tf32(a2, ph[2], pl[2]);
            split_tf32(a3, ph[3], pl[3]);
            #pragma unroll
            for (int ni = 0; ni < 8; ni++) {
                uint32_t vh[2], vl[2];
                split_tf32(Vs[c0*8 + tr][ni*8 + tq],     vh[0], vl[0]);
                split_tf32(Vs[c0*8 + tr + 4][ni*8 + tq], vh[1], vl[1]);
                mma_tf32(o[ni], ph, vh);
                mma_tf32(o[ni], ph, vl);
                mma_tf32(o[ni], pl, vh);
            }
        }
    }

    // ---- epilogue: y = o / l * gate ----
    const int rowa = qt*64 + r0, rowb = rowa + 8;
    float g0 = g_gate[(b*T + rowa) * NH + h] / l0r;
    float g1 = g_gate[(b*T + rowb) * NH + h] / l1r;
    #pragma unroll
    for (int ni = 0; ni < 8; ni++) {
        int col = ni*8 + 2*tr;
        size_t ba = ((size_t)(b*T + rowa) * NH + h) * HD + col;
        size_t bb = ((size_t)(b*T + rowb) * NH + h) * HD + col;
        *(float2*)(g_y + ba) = make_float2(o[ni][0] * g0, o[ni][1] * g0);
        *(float2*)(g_y + bb) = make_float2(o[ni][2] * g1, o[ni][3] * g1);
    }
}

// ---------------- launch ----------------
extern "C" void kernel_launch(void* const* d_in, const int* in_sizes, int n_in,
                              void* d_out, int out_size) {
    (void)in_sizes; (void)n_in; (void)out_size;
    const float* x  = (const float*)d_in[0];
    const float* qw = (const float*)d_in[1];
    const float* kw = (const float*)d_in[2];
    const float* vw = (const float*)d_in[3];
    const float* ow = (const float*)d_in[4];
    const float* ve = (const float*)d_in[5];
    const float* v0 = (const float*)d_in[6];
    const float* qg = (const float*)d_in[7];
    const float* vl = (const float*)d_in[8];
    const float* gw = (const float*)d_in[9];
    const float* gb = (const float*)d_in[10];

    float* out     = (float*)d_out;
    float* raw_out = out + (size_t)B * T * D;     // second output: raw_v

    // NTK-scaled base: T=2048 > TSL=1024
    const double nb = 10000.0 * pow((double)T / 1024.0, 64.0 / 62.0);

    // projections (tf32 3-pass: fp32-accurate)
    tf32_gemm3<<<dim3((NH*HD)/128,  (B*T)/128), 256>>>(x, -1, qw, nullptr, 0, B*T, NH*HD,  D);
    tf32_gemm3<<<dim3((NKV*HD)/128, (B*T)/128), 256>>>(x, -1, kw, nullptr, 1, B*T, NKV*HD, D);
    tf32_gemm3<<<dim3((NKV*HD)/128, (B*T)/128), 256>>>(x, -1, vw, nullptr, 2, B*T, NKV*HD, D);

    // v residual mix + raw_v output
    v_epilogue<<<(B*T*NKV*HD)/256, 256>>>(ve, v0, vl, raw_out);

    // rmsnorm + rope (+ q gain)
    rmsnorm_rope<<<(B*T*NH)/8,  256>>>(0, qg,      NH,  nb);
    rmsnorm_rope<<<(B*T*NKV)/8, 256>>>(1, nullptr, NKV, nb);

    // gate
    gate_kernel<<<B*T, 512>>>(x, gw, gb);

    // tensor-core attention (gate folded into epilogue)
    attn_mma<<<dim3(T/64, NH, B), 128>>>();

    // output projection (tf32 3-pass)
    tf32_gemm3<<<dim3(D/128, (B*T)/128), 256>>>(nullptr, 3, ow, out, -1, B*T, D, D);
}

// round 4
// speedup vs baseline: 2.0295x; 1.0036x over previous
#include <cuda_runtime.h>
#include <math.h>
#include <stdint.h>

#define B   2
#define T   2048
#define D   1024
#define NH  16
#define NKV 4
#define HD  64
#define GQ  4            // NH / NKV
#define EPSF 1.1920929e-07f
#define LOG2E 1.4426950408889634f

// ---------------- scratch (no allocations allowed) ----------------
__device__ float g_q[B*T*NH*HD];     // q projection -> normed/roped/gained q
__device__ float g_k[B*T*NKV*HD];    // k projection -> normed/roped k
__device__ float g_v[B*T*NKV*HD];    // v projection -> mixed v
__device__ float g_y[B*T*NH*HD];     // attention output (gate folded in)
__device__ float g_gate[B*T*NH];     // sigmoid gate per (b,t,head)

__device__ __forceinline__ float* scratch_buf(int id) {
    switch (id) {
        case 0: return g_q;
        case 1: return g_k;
        case 2: return g_v;
        default: return g_y;
    }
}

// ---------------- tf32 helpers ----------------
__device__ __forceinline__ float to_tf32(float x) {
    float r;
    asm("cvt.rna.tf32.f32 %0, %1;" : "=f"(r) : "f"(x));
    return r;
}

__device__ __forceinline__ void mma_tf32(float* c, const uint32_t* a, const uint32_t* b) {
    asm volatile(
        "mma.sync.aligned.m16n8k8.row.col.f32.tf32.tf32.f32 "
        "{%0,%1,%2,%3}, {%4,%5,%6,%7}, {%8,%9}, {%0,%1,%2,%3};\n"
        : "+f"(c[0]), "+f"(c[1]), "+f"(c[2]), "+f"(c[3])
        : "r"(a[0]), "r"(a[1]), "r"(a[2]), "r"(a[3]), "r"(b[0]), "r"(b[1]));
}

// split x into tf32 hi + tf32 lo
__device__ __forceinline__ void split_tf32(float x, uint32_t& hi, uint32_t& lo) {
    float h = to_tf32(x);
    hi = __float_as_uint(h);
    lo = __float_as_uint(to_tf32(x - h));
}

// ---------------- tf32 3-pass GEMM: C[M,N] = A[M,K] @ W[N,K]^T (fp32-accurate) ----------------
// CTA tile 128x128, BK=16, 256 threads (8 warps, 2x4), warp tile 64x32.
#define GSTRIDE 20
__global__ __launch_bounds__(256)
void tf32_gemm3(const float* __restrict__ Aext, int Abuf,
                const float* __restrict__ W,
                float* __restrict__ Cext, int Cbuf,
                int M, int N, int K) {
    const float* A = Aext ? Aext : scratch_buf(Abuf);
    float*       C = Cext ? Cext : scratch_buf(Cbuf);

    __shared__ float As[2][128 * GSTRIDE];
    __shared__ float Bs[2][128 * GSTRIDE];

    const int tid  = threadIdx.x;
    const int lane = tid & 31;
    const int w    = tid >> 5;
    const int wm   = w & 1;
    const int wn   = w >> 1;
    const int tq   = lane >> 2;
    const int tr   = lane & 3;

    const int m0 = blockIdx.y * 128;
    const int n0 = blockIdx.x * 128;

    const int lrow = tid >> 2;
    const int lcol = (tid & 3) * 4;

    const float* aN = A + (size_t)(m0 + lrow) * K + lcol;
    const float* bN = W + (size_t)(n0 + lrow) * K + lcol;

    float c[16][4];
    #pragma unroll
    for (int i = 0; i < 16; i++)
        #pragma unroll
        for (int j = 0; j < 4; j++) c[i][j] = 0.f;

    {
        float4 a0 = *(const float4*)(aN);
        float4 a1 = *(const float4*)(aN + (size_t)64 * K);
        float4 b0 = *(const float4*)(bN);
        float4 b1 = *(const float4*)(bN + (size_t)64 * K);
        float* as = As[0]; float* bs = Bs[0];
        int o0 = lrow * GSTRIDE + lcol;
        int o1 = (lrow + 64) * GSTRIDE + lcol;
        as[o0+0]=a0.x; as[o0+1]=a0.y; as[o0+2]=a0.z; as[o0+3]=a0.w;
        as[o1+0]=a1.x; as[o1+1]=a1.y; as[o1+2]=a1.z; as[o1+3]=a1.w;
        bs[o0+0]=b0.x; bs[o0+1]=b0.y; bs[o0+2]=b0.z; bs[o0+3]=b0.w;
        bs[o1+0]=b1.x; bs[o1+1]=b1.y; bs[o1+2]=b1.z; bs[o1+3]=b1.w;
    }
    __syncthreads();

    const int niter = K / 16;
    int cur = 0;
    for (int it = 0; it < niter; it++) {
        float4 pa0, pa1, pb0, pb1;
        const bool has_next = (it + 1 < niter);
        if (has_next) {
            int k0 = (it + 1) * 16;
            pa0 = *(const float4*)(aN + k0);
            pa1 = *(const float4*)(aN + (size_t)64 * K + k0);
            pb0 = *(const float4*)(bN + k0);
            pb1 = *(const float4*)(bN + (size_t)64 * K + k0);
        }

        const float* as = As[cur];
        const float* bs = Bs[cur];
        #pragma unroll
        for (int ks = 0; ks < 2; ks++) {
            const int kb = ks * 8;
            uint32_t ah[4][4], al[4][4], bh[4][2], bl[4][2];
            #pragma unroll
            for (int mi = 0; mi < 4; mi++) {
                int r = wm * 64 + mi * 16 + tq;
                split_tf32(as[r * GSTRIDE + kb + tr],           ah[mi][0], al[mi][0]);
                split_tf32(as[(r + 8) * GSTRIDE + kb + tr],     ah[mi][1], al[mi][1]);
                split_tf32(as[r * GSTRIDE + kb + tr + 4],       ah[mi][2], al[mi][2]);
                split_tf32(as[(r + 8) * GSTRIDE + kb + tr + 4], ah[mi][3], al[mi][3]);
            }
            #pragma unroll
            for (int ni = 0; ni < 4; ni++) {
                int nrow = wn * 32 + ni * 8 + tq;
                split_tf32(bs[nrow * GSTRIDE + kb + tr],     bh[ni][0], bl[ni][0]);
                split_tf32(bs[nrow * GSTRIDE + kb + tr + 4], bh[ni][1], bl[ni][1]);
            }
            #pragma unroll
            for (int mi = 0; mi < 4; mi++)
                #pragma unroll
                for (int ni = 0; ni < 4; ni++) {
                    mma_tf32(c[mi * 4 + ni], ah[mi], bh[ni]);
                    mma_tf32(c[mi * 4 + ni], ah[mi], bl[ni]);
                    mma_tf32(c[mi * 4 + ni], al[mi], bh[ni]);
                }
        }

        if (has_next) {
            int nxt = cur ^ 1;
            float* asx = As[nxt]; float* bsx = Bs[nxt];
            int o0 = lrow * GSTRIDE + lcol;
            int o1 = (lrow + 64) * GSTRIDE + lcol;
            asx[o0+0]=pa0.x; asx[o0+1]=pa0.y; asx[o0+2]=pa0.z; asx[o0+3]=pa0.w;
            asx[o1+0]=pa1.x; asx[o1+1]=pa1.y; asx[o1+2]=pa1.z; asx[o1+3]=pa1.w;
            bsx[o0+0]=pb0.x; bsx[o0+1]=pb0.y; bsx[o0+2]=pb0.z; bsx[o0+3]=pb0.w;
            bsx[o1+0]=pb1.x; bsx[o1+1]=pb1.y; bsx[o1+2]=pb1.z; bsx[o1+3]=pb1.w;
            __syncthreads();
            cur = nxt;
        }
    }

    #pragma unroll
    for (int mi = 0; mi < 4; mi++) {
        #pragma unroll
        for (int ni = 0; ni < 4; ni++) {
            int row = m0 + wm * 64 + mi * 16 + tq;
            int col = n0 + wn * 32 + ni * 8 + 2 * tr;
            float* cp = c[mi * 4 + ni];
            *(float2*)(C + (size_t)row * N + col)       = make_float2(cp[0], cp[1]);
            *(float2*)(C + (size_t)(row + 8) * N + col) = make_float2(cp[2], cp[3]);
        }
    }
}

// ---------------- V epilogue: raw_v = vproj + ve ; v = l0*v0 + l1*raw ----------------
__global__ void v_epilogue(const float* __restrict__ ve, const float* __restrict__ v0,
                           const float* __restrict__ lam, float* __restrict__ raw_out) {
    int i = blockIdx.x * 256 + threadIdx.x;
    float raw = g_v[i] + ve[i];
    raw_out[i] = raw;
    g_v[i] = lam[0] * v0[i] + lam[1] * raw;
}

// ---------------- RMSNorm + RoPE (+ per-head gain) in place; one warp per row ----------------
__global__ void rmsnorm_rope(int buf, const float* __restrict__ gain, int H, double nb) {
    float* base = scratch_buf(buf);
    int row  = blockIdx.x * 8 + (threadIdx.x >> 5);
    int lane = threadIdx.x & 31;
    int t = (row / H) % T;
    int h = row % H;
    float* p = base + (size_t)row * HD;

    float a  = p[lane];
    float b2 = p[lane + 32];
    float ss = a*a + b2*b2;
    #pragma unroll
    for (int o = 16; o; o >>= 1) ss += __shfl_xor_sync(0xffffffffu, ss, o);
    float r = rsqrtf(ss * (1.0f/HD) + EPSF);
    a *= r; b2 *= r;

    float inv = (float)pow(nb, -(double)(2*lane) / (double)HD);
    float fr  = (float)t * inv;
    float c = (float)cos((double)fr);
    float s = (float)sin((double)fr);

    float o1 =  a*c + b2*s;
    float o2 = -a*s + b2*c;
    if (gain) { float gg = gain[h]; o1 *= gg; o2 *= gg; }
    p[lane]      = o1;
    p[lane + 32] = o2;
}

// ---------------- gate: sigmoid(x @ gate_w^T + gate_b), one block per (b,t) ----------------
__global__ void gate_kernel(const float* __restrict__ x, const float* __restrict__ gw,
                            const float* __restrict__ gb) {
    __shared__ float xs[D];
    int bt = blockIdx.x;
    for (int i = threadIdx.x; i < D; i += 512) xs[i] = x[(size_t)bt * D + i];
    __syncthreads();
    int h = threadIdx.x >> 5, lane = threadIdx.x & 31;
    const float* w = gw + (size_t)h * D;
    float s = 0.f;
    for (int i = lane; i < D; i += 32) s += xs[i] * w[i];
    #pragma unroll
    for (int o = 16; o; o >>= 1) s += __shfl_xor_sync(0xffffffffu, s, o);
    if (lane == 0) g_gate[bt * NH + h] = 1.0f / (1.0f + __expf(-(s + gb[h])));
}

// ---------------- tensor-core causal flash attention ----------------
// 4 warps, 64 q rows per CTA (16/warp), 64-kv tiles. tf32 3-pass MMAs,
// fp32 online softmax in fragments, gate folded into epilogue.
__global__ __launch_bounds__(128)
void attn_mma() {
    __shared__ float Ks[64][68];   // pad 68: fragment LDS conflict-free
    __shared__ float Vs[64][72];   // pad 72: fragment LDS conflict-free

    const int qt = blockIdx.x, h = blockIdx.y, b = blockIdx.z;
    const int kv = h / GQ;
    const int tid = threadIdx.x;
    const int w = tid >> 5, lane = tid & 31;
    const int tq = lane >> 2, tr = lane & 3;
    const int r0 = w * 16 + tq;      // warp-local q row (and +8)

    // ---- stage Q tile into Ks, build persistent hi/lo Q fragments ----
    for (int i = tid; i < 64 * 16; i += 128) {
        int r = i >> 4, c4 = (i & 15) * 4;
        float4 v = *(const float4*)(g_q + ((size_t)(b*T + qt*64 + r) * NH + h) * HD + c4);
        Ks[r][c4] = v.x; Ks[r][c4+1] = v.y; Ks[r][c4+2] = v.z; Ks[r][c4+3] = v.w;
    }
    __syncthreads();

    uint32_t qhi[8][4], qlo[8][4];
    #pragma unroll
    for (int kb = 0; kb < 8; kb++) {
        split_tf32(Ks[r0][kb*8 + tr],       qhi[kb][0], qlo[kb][0]);
        split_tf32(Ks[r0 + 8][kb*8 + tr],   qhi[kb][1], qlo[kb][1]);
        split_tf32(Ks[r0][kb*8 + tr + 4],   qhi[kb][2], qlo[kb][2]);
        split_tf32(Ks[r0 + 8][kb*8 + tr+4], qhi[kb][3], qlo[kb][3]);
    }
    __syncthreads();

    float o[8][4];
    #pragma unroll
    for (int ni = 0; ni < 8; ni++)
        #pragma unroll
        for (int j = 0; j < 4; j++) o[ni][j] = 0.f;
    float m0r = -1e30f, m1r = -1e30f, l0r = 0.f, l1r = 0.f;

    const int ntiles = qt + 1;
    for (int kt = 0; kt < ntiles; kt++) {
        const int t0 = kt * 64;
        __syncthreads();
        for (int i = tid; i < 64 * 16; i += 128) {
            int r = i >> 4, c4 = (i & 15) * 4;
            size_t base = ((size_t)(b*T + t0 + r) * NKV + kv) * HD + c4;
            float4 kk = *(const float4*)(g_k + base);
            float4 vv = *(const float4*)(g_v + base);
            Ks[r][c4] = kk.x; Ks[r][c4+1] = kk.y; Ks[r][c4+2] = kk.z; Ks[r][c4+3] = kk.w;
            Vs[r][c4] = vv.x; Vs[r][c4+1] = vv.y; Vs[r][c4+2] = vv.z; Vs[r][c4+3] = vv.w;
        }
        __syncthreads();

        // ---- scores S = Q @ K^T (3-pass tf32) ----
        float s[8][4];
        #pragma unroll
        for (int ni = 0; ni < 8; ni++) {
            s[ni][0] = s[ni][1] = s[ni][2] = s[ni][3] = 0.f;
            #pragma unroll
            for (int kb = 0; kb < 8; kb++) {
                uint32_t bh[2], bl[2];
                split_tf32(Ks[ni*8 + tq][kb*8 + tr],     bh[0], bl[0]);
                split_tf32(Ks[ni*8 + tq][kb*8 + tr + 4], bh[1], bl[1]);
                mma_tf32(s[ni], qhi[kb], bh);
                mma_tf32(s[ni], qhi[kb], bl);
                mma_tf32(s[ni], qlo[kb], bh);
            }
        }

        // ---- causal mask (diagonal tile only) ----
        const int rowa = qt*64 + r0, rowb = rowa + 8;
        if (kt == qt) {
            #pragma unroll
            for (int ni = 0; ni < 8; ni++) {
                int col = t0 + ni*8 + 2*tr;
                if (col     > rowa) s[ni][0] = -1e30f;
                if (col + 1 > rowa) s[ni][1] = -1e30f;
                if (col     > rowb) s[ni][2] = -1e30f;
                if (col + 1 > rowb) s[ni][3] = -1e30f;
            }
        }

        // ---- online softmax (logits = s * 0.125) ----
        const float SC = 0.125f;
        float mx0 = -1e30f, mx1 = -1e30f;
        #pragma unroll
        for (int ni = 0; ni < 8; ni++) {
            mx0 = fmaxf(mx0, fmaxf(s[ni][0], s[ni][1]));
            mx1 = fmaxf(mx1, fmaxf(s[ni][2], s[ni][3]));
        }
        mx0 = fmaxf(mx0, __shfl_xor_sync(0xffffffffu, mx0, 1));
        mx0 = fmaxf(mx0, __shfl_xor_sync(0xffffffffu, mx0, 2));
        mx1 = fmaxf(mx1, __shfl_xor_sync(0xffffffffu, mx1, 1));
        mx1 = fmaxf(mx1, __shfl_xor_sync(0xffffffffu, mx1, 2));
        float mn0 = fmaxf(m0r, mx0 * SC);
        float mn1 = fmaxf(m1r, mx1 * SC);
        float al0 = exp2f((m0r - mn0) * LOG2E);
        float al1 = exp2f((m1r - mn1) * LOG2E);
        m0r = mn0; m1r = mn1;

        float sum0 = 0.f, sum1 = 0.f;
        #pragma unroll
        for (int ni = 0; ni < 8; ni++) {
            float p0 = exp2f((s[ni][0] * SC - mn0) * LOG2E);
            float p1 = exp2f((s[ni][1] * SC - mn0) * LOG2E);
            float p2 = exp2f((s[ni][2] * SC - mn1) * LOG2E);
            float p3 = exp2f((s[ni][3] * SC - mn1) * LOG2E);
            s[ni][0] = p0; s[ni][1] = p1; s[ni][2] = p2; s[ni][3] = p3;
            sum0 += p0 + p1; sum1 += p2 + p3;
            o[ni][0] *= al0; o[ni][1] *= al0; o[ni][2] *= al1; o[ni][3] *= al1;
        }
        sum0 += __shfl_xor_sync(0xffffffffu, sum0, 1);
        sum0 += __shfl_xor_sync(0xffffffffu, sum0, 2);
        sum1 += __shfl_xor_sync(0xffffffffu, sum1, 1);
        sum1 += __shfl_xor_sync(0xffffffffu, sum1, 2);
        l0r = l0r * al0 + sum0;
        l1r = l1r * al1 + sum1;

        // ---- O += P @ V (3-pass tf32); C->A fragment conversion via shuffles ----
        const int basel = lane & ~3;
        #pragma unroll
        for (int c0 = 0; c0 < 8; c0++) {
            const int srcA = basel + (tr >> 1);
            const int srcB = srcA + 2;
            float pa0 = __shfl_sync(0xffffffffu, s[c0][0], srcA);
            float pa1 = __shfl_sync(0xffffffffu, s[c0][1], srcA);
            float pa2 = __shfl_sync(0xffffffffu, s[c0][2], srcA);
            float pa3 = __shfl_sync(0xffffffffu, s[c0][3], srcA);
            float pb0 = __shfl_sync(0xffffffffu, s[c0][0], srcB);
            float pb1 = __shfl_sync(0xffffffffu, s[c0][1], srcB);
            float pb2 = __shfl_sync(0xffffffffu, s[c0][2], srcB);
            float pb3 = __shfl_sync(0xffffffffu, s[c0][3], srcB);
            bool odd = (tr & 1);
            float a0 = odd ? pa1 : pa0;   // P[tq][8c0+tr]
            float a1 = odd ? pa3 : pa2;   // P[tq+8][8c0+tr]
            float a2 = odd ? pb1 : pb0;   // P[tq][8c0+tr+4]
            float a3 = odd ? pb3 : pb2;   // P[tq+8][8c0+tr+4]
            uint32_t ph[4], pl[4];
            split_tf32(a0, ph[0], pl[0]);
            split_tf32(a1, ph[1], pl[1]);
            split_tf32(a2, ph[2], pl[2]);
            split_tf32(a3, ph[3], pl[3]);
            #pragma unroll
            for (int ni = 0; ni < 8; ni++) {
                uint32_t vh[2], vl[2];
                split_tf32(Vs[c0*8 + tr][ni*8 + tq],     vh[0], vl[0]);
                split_tf32(Vs[c0*8 + tr + 4][ni*8 + tq], vh[1], vl[1]);
                mma_tf32(o[ni], ph, vh);
                mma_tf32(o[ni], ph, vl);
                mma_tf32(o[ni], pl, vh);
            }
        }
    }

    // ---- epilogue: y = o / l * gate ----
    const int rowa = qt*64 + r0, rowb = rowa + 8;
    float g0 = g_gate[(b*T + rowa) * NH + h] / l0r;
    float g1 = g_gate[(b*T + rowb) * NH + h] / l1r;
    #pragma unroll
    for (int ni = 0; ni < 8; ni++) {
        int col = ni*8 + 2*tr;
        size_t ba = ((size_t)(b*T + rowa) * NH + h) * HD + col;
        size_t bb = ((size_t)(b*T + rowb) * NH + h) * HD + col;
        *(float2*)(g_y + ba) = make_float2(o[ni][0] * g0, o[ni][1] * g0);
        *(float2*)(g_y + bb) = make_float2(o[ni][2] * g1, o[ni][3] * g1);
    }
}

// ---------------- launch ----------------
extern "C" void kernel_launch(void* const* d_in, const int* in_sizes, int n_in,
                              void* d_out, int out_size) {
    (void)in_sizes; (void)n_in; (void)out_size;
    const float* x  = (const float*)d_in[0];
    const float* qw = (const float*)d_in[1];
    const float* kw = (const float*)d_in[2];
    const float* vw = (const float*)d_in[3];
    const float* ow = (const float*)d_in[4];
    const float* ve = (const float*)d_in[5];
    const float* v0 = (const float*)d_in[6];
    const float* qg = (const float*)d_in[7];
    const float* vl = (const float*)d_in[8];
    const float* gw = (const float*)d_in[9];
    const float* gb = (const float*)d_in[10];

    float* out     = (float*)d_out;
    float* raw_out = out + (size_t)B * T * D;     // second output: raw_v

    // NTK-scaled base: T=2048 > TSL=1024
    const double nb = 10000.0 * pow((double)T / 1024.0, 64.0 / 62.0);

    // projections (tf32 3-pass: fp32-accurate)
    tf32_gemm3<<<dim3((NH*HD)/128,  (B*T)/128), 256>>>(x, -1, qw, nullptr, 0, B*T, NH*HD,  D);
    tf32_gemm3<<<dim3((NKV*HD)/128, (B*T)/128), 256>>>(x, -1, kw, nullptr, 1, B*T, NKV*HD, D);
    tf32_gemm3<<<dim3((NKV*HD)/128, (B*T)/128), 256>>>(x, -1, vw, nullptr, 2, B*T, NKV*HD, D);

    // v residual mix + raw_v output
    v_epilogue<<<(B*T*NKV*HD)/256, 256>>>(ve, v0, vl, raw_out);

    // rmsnorm + rope (+ q gain)
    rmsnorm_rope<<<(B*T*NH)/8,  256>>>(0, qg,      NH,  nb);
    rmsnorm_rope<<<(B*T*NKV)/8, 256>>>(1, nullptr, NKV, nb);

    // gate
    gate_kernel<<<B*T, 512>>>(x, gw, gb);

    // tensor-core attention (gate folded into epilogue)
    attn_mma<<<dim3(T/64, NH, B), 128>>>();

    // output projection (tf32 3-pass)
    tf32_gemm3<<<dim3(D/128, (B*T)/128), 256>>>(nullptr, 3, ow, out, -1, B*T, D, D);
}

// round 5
// speedup vs baseline: 2.6660x; 1.3136x over previous
#include <cuda_runtime.h>
#include <math.h>
#include <stdint.h>

#define B   2
#define T   2048
#define D   1024
#define NH  16
#define NKV 4
#define HD  64
#define GQ  4            // NH / NKV
#define EPSF 1.1920929e-07f
#define LOG2E 1.4426950408889634f
#define PSTR 12          // GEMM smem word stride (8 data + 4 pad) -> conflict-free frags

// ---------------- scratch (no allocations allowed) ----------------
__device__ float g_q[B*T*NH*HD];     // q projection -> normed/roped/gained q
__device__ float g_k[B*T*NKV*HD];    // k projection -> normed/roped k
__device__ float g_v[B*T*NKV*HD];    // v projection -> mixed v
__device__ float g_y[B*T*NH*HD];     // attention output (gate folded in)
__device__ float g_gate[B*T*NH];     // sigmoid gate per (b,t,head)

__device__ __forceinline__ float* scratch_buf(int id) {
    switch (id) {
        case 0: return g_q;
        case 1: return g_k;
        case 2: return g_v;
        default: return g_y;
    }
}

// ---------------- bf16 helpers ----------------
__device__ __forceinline__ void mma_bf16(float* c, const uint32_t* a, const uint32_t* b) {
    asm volatile(
        "mma.sync.aligned.m16n8k16.row.col.f32.bf16.bf16.f32 "
        "{%0,%1,%2,%3}, {%4,%5,%6,%7}, {%8,%9}, {%0,%1,%2,%3};\n"
        : "+f"(c[0]), "+f"(c[1]), "+f"(c[2]), "+f"(c[3])
        : "r"(a[0]), "r"(a[1]), "r"(a[2]), "r"(a[3]), "r"(b[0]), "r"(b[1]));
}

// pack (x0,x1) -> bf16x2 hi word (low half = x0) and bf16x2 residual word
__device__ __forceinline__ void split2_pack(float x0, float x1, uint32_t& wh, uint32_t& wm) {
    asm("cvt.rn.bf16x2.f32 %0, %1, %2;" : "=r"(wh) : "f"(x1), "f"(x0));
    float h0 = __uint_as_float(wh << 16);
    float h1 = __uint_as_float(wh & 0xffff0000u);
    asm("cvt.rn.bf16x2.f32 %0, %1, %2;" : "=r"(wm) : "f"(x1 - h1), "f"(x0 - h0));
}

// ---------------- bf16-split GEMM: C[M,N] = A[M,K] @ W[N,K]^T (fp32-accurate) ----------------
// CTA 128x128, BK=16, 256 threads (8 warps 2x4), warp tile 64x32.
// Smem: double-buffered pre-split packed bf16x2 planes, 48KB total.
__global__ __launch_bounds__(256)
void gemm_bf16(const float* __restrict__ Aext, int Abuf,
               const float* __restrict__ W,
               float* __restrict__ Cext, int Cbuf,
               int M, int N, int K) {
    const float* A = Aext ? Aext : scratch_buf(Abuf);
    float*       C = Cext ? Cext : scratch_buf(Cbuf);

    __shared__ uint32_t Ah[2][128*PSTR], Am[2][128*PSTR];
    __shared__ uint32_t Bh[2][128*PSTR], Bm[2][128*PSTR];

    const int tid  = threadIdx.x;
    const int lane = tid & 31;
    const int w    = tid >> 5;
    const int wm   = w & 1;      // 0..1 -> 64 rows
    const int wn   = w >> 1;     // 0..3 -> 32 cols
    const int tq   = lane >> 2;
    const int tr   = lane & 3;

    const int m0 = blockIdx.y * 128;
    const int n0 = blockIdx.x * 128;

    const int lrow = tid >> 1;           // 0..127
    const int lc8  = (tid & 1) * 8;      // fp32 col 0 or 8
    const int lw   = (tid & 1) * 4;      // word col 0 or 4

    const float* aN = A + (size_t)(m0 + lrow) * K + lc8;
    const float* bN = W + (size_t)(n0 + lrow) * K + lc8;

    float c[16][4];
    #pragma unroll
    for (int i = 0; i < 16; i++)
        #pragma unroll
        for (int j = 0; j < 4; j++) c[i][j] = 0.f;

    // fill buffer 0
    {
        float4 a0 = *(const float4*)(aN);
        float4 a1 = *(const float4*)(aN + 4);
        float4 b0 = *(const float4*)(bN);
        float4 b1 = *(const float4*)(bN + 4);
        uint32_t h[4], m[4];
        split2_pack(a0.x, a0.y, h[0], m[0]); split2_pack(a0.z, a0.w, h[1], m[1]);
        split2_pack(a1.x, a1.y, h[2], m[2]); split2_pack(a1.z, a1.w, h[3], m[3]);
        *(uint4*)&Ah[0][lrow*PSTR + lw] = make_uint4(h[0], h[1], h[2], h[3]);
        *(uint4*)&Am[0][lrow*PSTR + lw] = make_uint4(m[0], m[1], m[2], m[3]);
        split2_pack(b0.x, b0.y, h[0], m[0]); split2_pack(b0.z, b0.w, h[1], m[1]);
        split2_pack(b1.x, b1.y, h[2], m[2]); split2_pack(b1.z, b1.w, h[3], m[3]);
        *(uint4*)&Bh[0][lrow*PSTR + lw] = make_uint4(h[0], h[1], h[2], h[3]);
        *(uint4*)&Bm[0][lrow*PSTR + lw] = make_uint4(m[0], m[1], m[2], m[3]);
    }
    __syncthreads();

    const int niter = K / 16;
    int cur = 0;
    for (int it = 0; it < niter; it++) {
        float4 pa0, pa1, pb0, pb1;
        const bool has_next = (it + 1 < niter);
        if (has_next) {
            int k0 = (it + 1) * 16;
            pa0 = *(const float4*)(aN + k0);
            pa1 = *(const float4*)(aN + k0 + 4);
            pb0 = *(const float4*)(bN + k0);
            pb1 = *(const float4*)(bN + k0 + 4);
        }

        const uint32_t* ah = Ah[cur]; const uint32_t* am = Am[cur];
        const uint32_t* bh = Bh[cur]; const uint32_t* bm = Bm[cur];

        uint32_t afh[4][4], afm[4][4], bfh[4][2], bfm[4][2];
        #pragma unroll
        for (int mi = 0; mi < 4; mi++) {
            int r = wm * 64 + mi * 16 + tq;
            afh[mi][0] = ah[r*PSTR + tr];     afh[mi][1] = ah[(r+8)*PSTR + tr];
            afh[mi][2] = ah[r*PSTR + tr + 4]; afh[mi][3] = ah[(r+8)*PSTR + tr + 4];
            afm[mi][0] = am[r*PSTR + tr];     afm[mi][1] = am[(r+8)*PSTR + tr];
            afm[mi][2] = am[r*PSTR + tr + 4]; afm[mi][3] = am[(r+8)*PSTR + tr + 4];
        }
        #pragma unroll
        for (int ni = 0; ni < 4; ni++) {
            int rn = wn * 32 + ni * 8 + tq;
            bfh[ni][0] = bh[rn*PSTR + tr]; bfh[ni][1] = bh[rn*PSTR + tr + 4];
            bfm[ni][0] = bm[rn*PSTR + tr]; bfm[ni][1] = bm[rn*PSTR + tr + 4];
        }
        #pragma unroll
        for (int mi = 0; mi < 4; mi++)
            #pragma unroll
            for (int ni = 0; ni < 4; ni++) {
                mma_bf16(c[mi*4+ni], afh[mi], bfh[ni]);
                mma_bf16(c[mi*4+ni], afh[mi], bfm[ni]);
                mma_bf16(c[mi*4+ni], afm[mi], bfh[ni]);
            }

        if (has_next) {
            int nxt = cur ^ 1;
            uint32_t h[4], m[4];
            split2_pack(pa0.x, pa0.y, h[0], m[0]); split2_pack(pa0.z, pa0.w, h[1], m[1]);
            split2_pack(pa1.x, pa1.y, h[2], m[2]); split2_pack(pa1.z, pa1.w, h[3], m[3]);
            *(uint4*)&Ah[nxt][lrow*PSTR + lw] = make_uint4(h[0], h[1], h[2], h[3]);
            *(uint4*)&Am[nxt][lrow*PSTR + lw] = make_uint4(m[0], m[1], m[2], m[3]);
            split2_pack(pb0.x, pb0.y, h[0], m[0]); split2_pack(pb0.z, pb0.w, h[1], m[1]);
            split2_pack(pb1.x, pb1.y, h[2], m[2]); split2_pack(pb1.z, pb1.w, h[3], m[3]);
            *(uint4*)&Bh[nxt][lrow*PSTR + lw] = make_uint4(h[0], h[1], h[2], h[3]);
            *(uint4*)&Bm[nxt][lrow*PSTR + lw] = make_uint4(m[0], m[1], m[2], m[3]);
            __syncthreads();
            cur = nxt;
        }
    }

    #pragma unroll
    for (int mi = 0; mi < 4; mi++)
        #pragma unroll
        for (int ni = 0; ni < 4; ni++) {
            int row = m0 + wm*64 + mi*16 + tq;
            int col = n0 + wn*32 + ni*8 + 2*tr;
            float* cp = c[mi*4+ni];
            *(float2*)(C + (size_t)row * N + col)       = make_float2(cp[0], cp[1]);
            *(float2*)(C + (size_t)(row + 8) * N + col) = make_float2(cp[2], cp[3]);
        }
}

// ---------------- V epilogue: raw_v = vproj + ve ; v = l0*v0 + l1*raw ----------------
__global__ void v_epilogue(const float* __restrict__ ve, const float* __restrict__ v0,
                           const float* __restrict__ lam, float* __restrict__ raw_out) {
    int i = blockIdx.x * 256 + threadIdx.x;
    float raw = g_v[i] + ve[i];
    raw_out[i] = raw;
    g_v[i] = lam[0] * v0[i] + lam[1] * raw;
}

// ---------------- RMSNorm + RoPE (+ per-head gain) in place; one warp per row ----------------
__global__ void rmsnorm_rope(int buf, const float* __restrict__ gain, int H, double nb) {
    float* base = scratch_buf(buf);
    int row  = blockIdx.x * 8 + (threadIdx.x >> 5);
    int lane = threadIdx.x & 31;
    int t = (row / H) % T;
    int h = row % H;
    float* p = base + (size_t)row * HD;

    float a  = p[lane];
    float b2 = p[lane + 32];
    float ss = a*a + b2*b2;
    #pragma unroll
    for (int o = 16; o; o >>= 1) ss += __shfl_xor_sync(0xffffffffu, ss, o);
    float r = rsqrtf(ss * (1.0f/HD) + EPSF);
    a *= r; b2 *= r;

    float inv = (float)pow(nb, -(double)(2*lane) / (double)HD);
    float fr  = (float)t * inv;
    float c = (float)cos((double)fr);
    float s = (float)sin((double)fr);

    float o1 =  a*c + b2*s;
    float o2 = -a*s + b2*c;
    if (gain) { float gg = gain[h]; o1 *= gg; o2 *= gg; }
    p[lane]      = o1;
    p[lane + 32] = o2;
}

// ---------------- gate: sigmoid(x @ gate_w^T + gate_b), one block per (b,t) ----------------
__global__ void gate_kernel(const float* __restrict__ x, const float* __restrict__ gw,
                            const float* __restrict__ gb) {
    __shared__ float xs[D];
    int bt = blockIdx.x;
    for (int i = threadIdx.x; i < D; i += 512) xs[i] = x[(size_t)bt * D + i];
    __syncthreads();
    int h = threadIdx.x >> 5, lane = threadIdx.x & 31;
    const float* w = gw + (size_t)h * D;
    float s = 0.f;
    for (int i = lane; i < D; i += 32) s += xs[i] * w[i];
    #pragma unroll
    for (int o = 16; o; o >>= 1) s += __shfl_xor_sync(0xffffffffu, s, o);
    if (lane == 0) g_gate[bt * NH + h] = 1.0f / (1.0f + __expf(-(s + gb[h])));
}

// ---------------- bf16 tensor-core causal flash attention ----------------
// 4 warps, 64 q rows per CTA (16/warp), 64-kv tiles. bf16 split MMAs, zero shuffles
// for the P->A conversion (C-fragment n-pairs == A-fragment k-pairs).
__global__ __launch_bounds__(128)
void attn_bf16() {
    __shared__ float Ks[64][68];
    __shared__ float Vs[64][68];

    const int qt = (int)gridDim.x - 1 - (int)blockIdx.x;   // heavy tiles first
    const int h = blockIdx.y, b = blockIdx.z;
    const int kv = h / GQ;
    const int tid = threadIdx.x;
    const int w = tid >> 5, lane = tid & 31;
    const int tq = lane >> 2, tr = lane & 3;
    const int r0 = w * 16 + tq;      // warp-local q row (and +8)

    // ---- stage Q tile, build persistent hi/mid Q fragments (4 k16 blocks) ----
    for (int i = tid; i < 64 * 16; i += 128) {
        int r = i >> 4, c4 = (i & 15) * 4;
        float4 v = *(const float4*)(g_q + ((size_t)(b*T + qt*64 + r) * NH + h) * HD + c4);
        Ks[r][c4] = v.x; Ks[r][c4+1] = v.y; Ks[r][c4+2] = v.z; Ks[r][c4+3] = v.w;
    }
    __syncthreads();

    uint32_t qh[4][4], qm[4][4];
    #pragma unroll
    for (int kb = 0; kb < 4; kb++) {
        int k0 = kb*16 + 2*tr;
        split2_pack(Ks[r0][k0],       Ks[r0][k0+1],       qh[kb][0], qm[kb][0]);
        split2_pack(Ks[r0+8][k0],     Ks[r0+8][k0+1],     qh[kb][1], qm[kb][1]);
        split2_pack(Ks[r0][k0+8],     Ks[r0][k0+9],       qh[kb][2], qm[kb][2]);
        split2_pack(Ks[r0+8][k0+8],   Ks[r0+8][k0+9],     qh[kb][3], qm[kb][3]);
    }
    __syncthreads();

    float o[8][4];
    #pragma unroll
    for (int ni = 0; ni < 8; ni++)
        #pragma unroll
        for (int j = 0; j < 4; j++) o[ni][j] = 0.f;
    float m0r = -1e30f, m1r = -1e30f, l0r = 0.f, l1r = 0.f;

    for (int kt = 0; kt <= qt; kt++) {
        const int t0 = kt * 64;
        __syncthreads();
        for (int i = tid; i < 64 * 16; i += 128) {
            int r = i >> 4, c4 = (i & 15) * 4;
            size_t base = ((size_t)(b*T + t0 + r) * NKV + kv) * HD + c4;
            float4 kk = *(const float4*)(g_k + base);
            float4 vv = *(const float4*)(g_v + base);
            Ks[r][c4] = kk.x; Ks[r][c4+1] = kk.y; Ks[r][c4+2] = kk.z; Ks[r][c4+3] = kk.w;
            Vs[r][c4] = vv.x; Vs[r][c4+1] = vv.y; Vs[r][c4+2] = vv.z; Vs[r][c4+3] = vv.w;
        }
        __syncthreads();

        // ---- S = Q @ K^T (bf16 split) ----
        float s[8][4];
        #pragma unroll
        for (int ni = 0; ni < 8; ni++) {
            s[ni][0] = s[ni][1] = s[ni][2] = s[ni][3] = 0.f;
            const int kn = ni*8 + tq;
            #pragma unroll
            for (int kb = 0; kb < 4; kb++) {
                int k0 = kb*16 + 2*tr;
                uint32_t bh[2], bm[2];
                split2_pack(Ks[kn][k0],   Ks[kn][k0+1], bh[0], bm[0]);
                split2_pack(Ks[kn][k0+8], Ks[kn][k0+9], bh[1], bm[1]);
                mma_bf16(s[ni], qh[kb], bh);
                mma_bf16(s[ni], qh[kb], bm);
                mma_bf16(s[ni], qm[kb], bh);
            }
        }

        // ---- causal mask (diagonal tile only) ----
        const int rowa = qt*64 + r0, rowb = rowa + 8;
        if (kt == qt) {
            #pragma unroll
            for (int ni = 0; ni < 8; ni++) {
                int col = t0 + ni*8 + 2*tr;
                if (col     > rowa) s[ni][0] = -1e30f;
                if (col + 1 > rowa) s[ni][1] = -1e30f;
                if (col     > rowb) s[ni][2] = -1e30f;
                if (col + 1 > rowb) s[ni][3] = -1e30f;
            }
        }

        // ---- online softmax (logits = s * 0.125) ----
        const float SC = 0.125f;
        float mx0 = -1e30f, mx1 = -1e30f;
        #pragma unroll
        for (int ni = 0; ni < 8; ni++) {
            mx0 = fmaxf(mx0, fmaxf(s[ni][0], s[ni][1]));
            mx1 = fmaxf(mx1, fmaxf(s[ni][2], s[ni][3]));
        }
        mx0 = fmaxf(mx0, __shfl_xor_sync(0xffffffffu, mx0, 1));
        mx0 = fmaxf(mx0, __shfl_xor_sync(0xffffffffu, mx0, 2));
        mx1 = fmaxf(mx1, __shfl_xor_sync(0xffffffffu, mx1, 1));
        mx1 = fmaxf(mx1, __shfl_xor_sync(0xffffffffu, mx1, 2));
        float mn0 = fmaxf(m0r, mx0 * SC);
        float mn1 = fmaxf(m1r, mx1 * SC);
        float al0 = exp2f((m0r - mn0) * LOG2E);
        float al1 = exp2f((m1r - mn1) * LOG2E);
        m0r = mn0; m1r = mn1;

        float sum0 = 0.f, sum1 = 0.f;
        #pragma unroll
        for (int ni = 0; ni < 8; ni++) {
            float p0 = exp2f((s[ni][0] * SC - mn0) * LOG2E);
            float p1 = exp2f((s[ni][1] * SC - mn0) * LOG2E);
            float p2 = exp2f((s[ni][2] * SC - mn1) * LOG2E);
            float p3 = exp2f((s[ni][3] * SC - mn1) * LOG2E);
            s[ni][0] = p0; s[ni][1] = p1; s[ni][2] = p2; s[ni][3] = p3;
            sum0 += p0 + p1; sum1 += p2 + p3;
            o[ni][0] *= al0; o[ni][1] *= al0; o[ni][2] *= al1; o[ni][3] *= al1;
        }
        sum0 += __shfl_xor_sync(0xffffffffu, sum0, 1);
        sum0 += __shfl_xor_sync(0xffffffffu, sum0, 2);
        sum1 += __shfl_xor_sync(0xffffffffu, sum1, 1);
        sum1 += __shfl_xor_sync(0xffffffffu, sum1, 2);
        l0r = l0r * al0 + sum0;
        l1r = l1r * al1 + sum1;

        // ---- O += P @ V (bf16 split); A-fragments straight from S C-fragments ----
        #pragma unroll
        for (int c0 = 0; c0 < 4; c0++) {
            uint32_t ph[4], pm[4];
            split2_pack(s[2*c0][0],   s[2*c0][1],   ph[0], pm[0]);   // row tq,   k=2tr..
            split2_pack(s[2*c0][2],   s[2*c0][3],   ph[1], pm[1]);   // row tq+8
            split2_pack(s[2*c0+1][0], s[2*c0+1][1], ph[2], pm[2]);   // k+8
            split2_pack(s[2*c0+1][2], s[2*c0+1][3], ph[3], pm[3]);
            const int ta = c0*16 + 2*tr;
            #pragma unroll
            for (int ni = 0; ni < 8; ni++) {
                const int dd = ni*8 + tq;
                uint32_t vh[2], vm[2];
                split2_pack(Vs[ta][dd],   Vs[ta+1][dd], vh[0], vm[0]);
                split2_pack(Vs[ta+8][dd], Vs[ta+9][dd], vh[1], vm[1]);
                mma_bf16(o[ni], ph, vh);
                mma_bf16(o[ni], ph, vm);
                mma_bf16(o[ni], pm, vh);
            }
        }
    }

    // ---- epilogue: y = o / l * gate ----
    const int rowa = qt*64 + r0, rowb = rowa + 8;
    float g0 = g_gate[(b*T + rowa) * NH + h] / l0r;
    float g1 = g_gate[(b*T + rowb) * NH + h] / l1r;
    #pragma unroll
    for (int ni = 0; ni < 8; ni++) {
        int col = ni*8 + 2*tr;
        size_t ba = ((size_t)(b*T + rowa) * NH + h) * HD + col;
        size_t bb = ((size_t)(b*T + rowb) * NH + h) * HD + col;
        *(float2*)(g_y + ba) = make_float2(o[ni][0] * g0, o[ni][1] * g0);
        *(float2*)(g_y + bb) = make_float2(o[ni][2] * g1, o[ni][3] * g1);
    }
}

// ---------------- launch ----------------
extern "C" void kernel_launch(void* const* d_in, const int* in_sizes, int n_in,
                              void* d_out, int out_size) {
    (void)in_sizes; (void)n_in; (void)out_size;
    const float* x  = (const float*)d_in[0];
    const float* qw = (const float*)d_in[1];
    const float* kw = (const float*)d_in[2];
    const float* vw = (const float*)d_in[3];
    const float* ow = (const float*)d_in[4];
    const float* ve = (const float*)d_in[5];
    const float* v0 = (const float*)d_in[6];
    const float* qg = (const float*)d_in[7];
    const float* vl = (const float*)d_in[8];
    const float* gw = (const float*)d_in[9];
    const float* gb = (const float*)d_in[10];

    float* out     = (float*)d_out;
    float* raw_out = out + (size_t)B * T * D;     // second output: raw_v

    // NTK-scaled base: T=2048 > TSL=1024
    const double nb = 10000.0 * pow((double)T / 1024.0, 64.0 / 62.0);

    // projections (bf16 split: fp32-accurate)
    gemm_bf16<<<dim3((NH*HD)/128,  (B*T)/128), 256>>>(x, -1, qw, nullptr, 0, B*T, NH*HD,  D);
    gemm_bf16<<<dim3((NKV*HD)/128, (B*T)/128), 256>>>(x, -1, kw, nullptr, 1, B*T, NKV*HD, D);
    gemm_bf16<<<dim3((NKV*HD)/128, (B*T)/128), 256>>>(x, -1, vw, nullptr, 2, B*T, NKV*HD, D);

    // v residual mix + raw_v output
    v_epilogue<<<(B*T*NKV*HD)/256, 256>>>(ve, v0, vl, raw_out);

    // rmsnorm + rope (+ q gain)
    rmsnorm_rope<<<(B*T*NH)/8,  256>>>(0, qg,      NH,  nb);
    rmsnorm_rope<<<(B*T*NKV)/8, 256>>>(1, nullptr, NKV, nb);

    // gate
    gate_kernel<<<B*T, 512>>>(x, gw, gb);

    // bf16 tensor-core attention (gate folded into epilogue)
    attn_bf16<<<dim3(T/64, NH, B), 128>>>();

    // output projection (bf16 split)
    gemm_bf16<<<dim3(D/128, (B*T)/128), 256>>>(nullptr, 3, ow, out, -1, B*T, D, D);
}